// round 8
// baseline (speedup 1.0000x reference)
#include <cuda_runtime.h>
#include <math.h>

#define CC 32
#define HH 256
#define WW 256
#define KP 9
#define EPSF 1e-12f
#define SEGO 62                 // output pixels per warp
#define NSEG 5                  // ceil(256/62)
#define WPB 4                   // warps per block
#define NT (WPB * 32)
#define HW (HH * WW)

__device__ __forceinline__ float2 ld2(const float* p) {
    return *reinterpret_cast<const float2*>(p);
}

__device__ __forceinline__ void weights9(const float* __restrict__ dot,
                                         const float* __restrict__ pn2,
                                         float fn2,
                                         float* __restrict__ wgt)
{
    float fn = fmaxf(sqrtf(fn2), EPSF);
    float cs[KP], ed[KP];
    float cmax = -1e30f, emax = -1e30f;
#pragma unroll
    for (int k = 0; k < KP; k++) {
        float pn = fmaxf(sqrtf(pn2[k]), EPSF);
        float cv = dot[k] / (pn * fn);
        float d2 = pn2[k] + fn2 - 2.0f * dot[k];
        float ev = -sqrtf(fmaxf(d2, 0.0f));
        cs[k] = cv; ed[k] = ev;
        cmax = fmaxf(cmax, cv);
        emax = fmaxf(emax, ev);
    }
    float csum = 0.0f, esum = 0.0f;
#pragma unroll
    for (int k = 0; k < KP; k++) {
        cs[k] = __expf(cs[k] - cmax); csum += cs[k];
        ed[k] = __expf(ed[k] - emax); esum += ed[k];
    }
    float ci = 0.5f / csum, ei = 0.5f / esum;
#pragma unroll
    for (int k = 0; k < KP; k++) wgt[k] = cs[k] * ci + ed[k] * ei;
}

template<bool XE>
__device__ __forceinline__ void body(
    int lane, int seg, int h, int b,
    const float* __restrict__ fe,
    const float* __restrict__ fu,
    float* __restrict__ out)
{
    const unsigned FULL = 0xffffffffu;
    const int w0 = seg * SEGO - 2;
    const int c0 = w0 + 2 * lane;       // even
    const int c1 = c0 + 1;
    const int ca = min(max(c0, 0), WW - 2);   // clamped even address col

    float mx0 = 1.0f, mx1 = 1.0f;
    if (XE) {
        mx0 = (c0 >= 0 && c0 < WW) ? 1.0f : 0.0f;
        mx1 = (c1 >= 0 && c1 < WW) ? 1.0f : 0.0f;
    }

    const bool y0 = (h > 0);
    const bool y2 = (h < HH - 1);

    const size_t rowoff = (((size_t)b * CC) * HH + h) * WW;
    const float* fup = fu + rowoff + ca;
    const float* fep = fe + rowoff + ca;

    // ---- pass 1: per-column scatter accumulators ----
    float uA[3] = {0,0,0}, mA[3] = {0,0,0}, wA[3] = {0,0,0}, qA[3] = {0,0,0};
    float uB[3] = {0,0,0}, mB[3] = {0,0,0}, wB[3] = {0,0,0}, qB[3] = {0,0,0};
    float fnA = 0.0f, fnB = 0.0f;

#pragma unroll 8
    for (int c = 0; c < CC; c++) {
        const float* p = fup + c * HW;
        float2 vt = make_float2(0.0f, 0.0f);
        float2 vb = make_float2(0.0f, 0.0f);
        if (y0) vt = ld2(p - WW);
        float2 vm = ld2(p);
        if (y2) vb = ld2(p + WW);
        float2 f  = ld2(fep + c * HW);
        if (XE) {
            vt.x *= mx0; vt.y *= mx1;
            vm.x *= mx0; vm.y *= mx1;
            vb.x *= mx0; vb.y *= mx1;
        }

        float fl = __shfl_up_sync(FULL, f.y, 1);    // f(c0-1)
        float fr = __shfl_down_sync(FULL, f.x, 1);  // f(c1+1)

        fnA = fmaf(f.x, f.x, fnA);
        fnB = fmaf(f.y, f.y, fnB);

        float vx, vy;
        vx = vt.x; vy = vt.y;
        uA[0] = fmaf(vx, f.y, uA[0]); mA[0] = fmaf(vx, f.x, mA[0]);
        wA[0] = fmaf(vx, fl,  wA[0]); qA[0] = fmaf(vx, vx,  qA[0]);
        uB[0] = fmaf(vy, fr,  uB[0]); mB[0] = fmaf(vy, f.y, mB[0]);
        wB[0] = fmaf(vy, f.x, wB[0]); qB[0] = fmaf(vy, vy,  qB[0]);
        vx = vm.x; vy = vm.y;
        uA[1] = fmaf(vx, f.y, uA[1]); mA[1] = fmaf(vx, f.x, mA[1]);
        wA[1] = fmaf(vx, fl,  wA[1]); qA[1] = fmaf(vx, vx,  qA[1]);
        uB[1] = fmaf(vy, fr,  uB[1]); mB[1] = fmaf(vy, f.y, mB[1]);
        wB[1] = fmaf(vy, f.x, wB[1]); qB[1] = fmaf(vy, vy,  qB[1]);
        vx = vb.x; vy = vb.y;
        uA[2] = fmaf(vx, f.y, uA[2]); mA[2] = fmaf(vx, f.x, mA[2]);
        wA[2] = fmaf(vx, fl,  wA[2]); qA[2] = fmaf(vx, vx,  qA[2]);
        uB[2] = fmaf(vy, fr,  uB[2]); mB[2] = fmaf(vy, f.y, mB[2]);
        wB[2] = fmaf(vy, f.x, wB[2]); qB[2] = fmaf(vy, vy,  qB[2]);
    }

    // ---- redistribute + softmax, px A (col c0) ----
    float wgtA[KP], wgtB[KP];
    {
        float dot[KP], pn2[KP];
#pragma unroll
        for (int d = 0; d < 3; d++) {
            dot[d*3 + 0] = __shfl_up_sync(FULL, uB[d], 1);   // u(c0-1)
            dot[d*3 + 1] = mA[d];
            dot[d*3 + 2] = wB[d];                            // w(c0+1)
            pn2[d*3 + 0] = __shfl_up_sync(FULL, qB[d], 1);
            pn2[d*3 + 1] = qA[d];
            pn2[d*3 + 2] = qB[d];
        }
        weights9(dot, pn2, fnA, wgtA);
    }
    // ---- px B (col c1) ----
    {
        float dot[KP], pn2[KP];
#pragma unroll
        for (int d = 0; d < 3; d++) {
            dot[d*3 + 0] = uA[d];                            // u(c1-1)
            dot[d*3 + 1] = mB[d];
            dot[d*3 + 2] = __shfl_down_sync(FULL, wA[d], 1); // w(c1+1)
            pn2[d*3 + 0] = qA[d];
            pn2[d*3 + 1] = qB[d];
            pn2[d*3 + 2] = __shfl_down_sync(FULL, qA[d], 1);
        }
        weights9(dot, pn2, fnB, wgtB);
    }

    // pre-shuffled neighbor weights
    float wlB0 = __shfl_up_sync(FULL, wgtB[2], 1);
    float wlB1 = __shfl_up_sync(FULL, wgtB[5], 1);
    float wlB2 = __shfl_up_sync(FULL, wgtB[8], 1);
    float wrA0 = __shfl_down_sync(FULL, wgtA[0], 1);
    float wrA1 = __shfl_down_sync(FULL, wgtA[3], 1);
    float wrA2 = __shfl_down_sync(FULL, wgtA[6], 1);

    const bool st0 = (lane >= 1) && (c0 >= 0) && (c0 < WW);
    const bool st1 = (lane <= 30) && (c1 >= 0) && (c1 < WW);
    float* ob = out + rowoff + ca;

    // ---- pass 2 ----
#pragma unroll 8
    for (int c = 0; c < CC; c++) {
        const float* p = fup + c * HW;
        float2 vt = make_float2(0.0f, 0.0f);
        float2 vb = make_float2(0.0f, 0.0f);
        if (y0) vt = ld2(p - WW);
        float2 vm = ld2(p);
        if (y2) vb = ld2(p + WW);
        float2 f  = ld2(fep + c * HW);
        if (XE) {
            vt.x *= mx0; vt.y *= mx1;
            vm.x *= mx0; vm.y *= mx1;
            vb.x *= mx0; vb.y *= mx1;
        }

        float accA = vt.x * wgtA[1];
        accA = fmaf(vm.x, wgtA[4], accA);
        accA = fmaf(vb.x, wgtA[7], accA);
        accA = fmaf(vt.y, wgtA[2], accA);
        accA = fmaf(vm.y, wgtA[5], accA);
        accA = fmaf(vb.y, wgtA[8], accA);
        float accB = vt.y * wgtB[1];
        accB = fmaf(vm.y, wgtB[4], accB);
        accB = fmaf(vb.y, wgtB[7], accB);
        accB = fmaf(vt.x, wgtB[0], accB);
        accB = fmaf(vm.x, wgtB[3], accB);
        accB = fmaf(vb.x, wgtB[6], accB);
        float cl = vt.x * wlB0;
        cl = fmaf(vm.x, wlB1, cl);
        cl = fmaf(vb.x, wlB2, cl);
        float cr = vt.y * wrA0;
        cr = fmaf(vm.y, wrA1, cr);
        cr = fmaf(vb.y, wrA2, cr);

        float fromR = __shfl_down_sync(FULL, cl, 1);
        float fromL = __shfl_up_sync(FULL, cr, 1);

        float oA = accA + fromL + f.x;
        float oB = accB + fromR + f.y;

        float* q = ob + c * HW;
        if (st0 && st1) {
            *reinterpret_cast<float2*>(q) = make_float2(oA, oB);
        } else {
            if (st0) q[0] = oA;
            if (st1) q[1] = oB;
        }
    }
}

__global__ __launch_bounds__(NT, 8) void asfr_kernel(
    const float* __restrict__ fe,
    const float* __restrict__ fu,
    float* __restrict__ out)
{
    const int lane = threadIdx.x & 31;
    const int wid  = threadIdx.x >> 5;
    const int seg  = blockIdx.x;
    const int h    = blockIdx.y * WPB + wid;
    const int b    = blockIdx.z;

    if (seg == 0 || seg == NSEG - 1)
        body<true>(lane, seg, h, b, fe, fu, out);
    else
        body<false>(lane, seg, h, b, fe, fu, out);
}

extern "C" void kernel_launch(void* const* d_in, const int* in_sizes, int n_in,
                              void* d_out, int out_size)
{
    (void)in_sizes; (void)n_in; (void)out_size;
    const float* fe = (const float*)d_in[0];
    const float* fu = (const float*)d_in[1];
    float* out = (float*)d_out;

    dim3 grid(NSEG, HH / WPB, 4);
    asfr_kernel<<<grid, NT>>>(fe, fu, out);
}

// round 9
// speedup vs baseline: 1.0736x; 1.0736x over previous
#include <cuda_runtime.h>
#include <math.h>

#define CC 32
#define HH 256
#define WW 256
#define KP 9
#define EPSF 1e-12f
#define SEGO 62                 // output pixels per warp
#define NSEG 5                  // ceil(256/62)
#define WPB 4                   // warps per block
#define NT (WPB * 32)
#define HW (HH * WW)

__device__ __forceinline__ float2 ld2(const float* p) {
    return *reinterpret_cast<const float2*>(p);
}

__device__ __forceinline__ void weights9(const float* __restrict__ dot,
                                         const float* __restrict__ pn2,
                                         float fn2,
                                         float* __restrict__ wgt)
{
    float fn = fmaxf(sqrtf(fn2), EPSF);
    float cs[KP], ed[KP];
    float cmax = -1e30f, emax = -1e30f;
#pragma unroll
    for (int k = 0; k < KP; k++) {
        float pn = fmaxf(sqrtf(pn2[k]), EPSF);
        float cv = dot[k] / (pn * fn);
        float d2 = pn2[k] + fn2 - 2.0f * dot[k];
        float ev = -sqrtf(fmaxf(d2, 0.0f));
        cs[k] = cv; ed[k] = ev;
        cmax = fmaxf(cmax, cv);
        emax = fmaxf(emax, ev);
    }
    float csum = 0.0f, esum = 0.0f;
#pragma unroll
    for (int k = 0; k < KP; k++) {
        cs[k] = __expf(cs[k] - cmax); csum += cs[k];
        ed[k] = __expf(ed[k] - emax); esum += ed[k];
    }
    float ci = 0.5f / csum, ei = 0.5f / esum;
#pragma unroll
    for (int k = 0; k < KP; k++) wgt[k] = cs[k] * ci + ed[k] * ei;
}

template<bool XE>
__device__ __forceinline__ void body(
    int lane, int seg, int h, int b,
    const float* __restrict__ fe,
    const float* __restrict__ fu,
    float* __restrict__ out)
{
    const unsigned FULL = 0xffffffffu;
    const int w0 = seg * SEGO - 2;
    const int c0 = w0 + 2 * lane;       // even
    const int c1 = c0 + 1;
    const int ca = min(max(c0, 0), WW - 2);   // clamped even address col

    float mx0 = 1.0f, mx1 = 1.0f;
    if (XE) {
        mx0 = (c0 >= 0 && c0 < WW) ? 1.0f : 0.0f;
        mx1 = (c1 >= 0 && c1 < WW) ? 1.0f : 0.0f;
    }

    const bool y0 = (h > 0);
    const bool y2 = (h < HH - 1);

    const size_t rowoff = (((size_t)b * CC) * HH + h) * WW;
    const float* fup = fu + rowoff + ca;
    const float* fep = fe + rowoff + ca;

    // ---- pass 1: per-column scatter accumulators ----
    float uA[3] = {0,0,0}, mA[3] = {0,0,0}, wA[3] = {0,0,0}, qA[3] = {0,0,0};
    float uB[3] = {0,0,0}, mB[3] = {0,0,0}, wB[3] = {0,0,0}, qB[3] = {0,0,0};
    float fnA = 0.0f, fnB = 0.0f;

#pragma unroll 4
    for (int c = 0; c < CC; c++) {
        const float* p = fup + c * HW;
        float2 vt = make_float2(0.0f, 0.0f);
        float2 vb = make_float2(0.0f, 0.0f);
        if (y0) vt = ld2(p - WW);
        float2 vm = ld2(p);
        if (y2) vb = ld2(p + WW);
        float2 f  = ld2(fep + c * HW);
        if (XE) {
            vt.x *= mx0; vt.y *= mx1;
            vm.x *= mx0; vm.y *= mx1;
            vb.x *= mx0; vb.y *= mx1;
        }

        float fl = __shfl_up_sync(FULL, f.y, 1);    // f(c0-1)
        float fr = __shfl_down_sync(FULL, f.x, 1);  // f(c1+1)

        fnA = fmaf(f.x, f.x, fnA);
        fnB = fmaf(f.y, f.y, fnB);

        float vx, vy;
        vx = vt.x; vy = vt.y;
        uA[0] = fmaf(vx, f.y, uA[0]); mA[0] = fmaf(vx, f.x, mA[0]);
        wA[0] = fmaf(vx, fl,  wA[0]); qA[0] = fmaf(vx, vx,  qA[0]);
        uB[0] = fmaf(vy, fr,  uB[0]); mB[0] = fmaf(vy, f.y, mB[0]);
        wB[0] = fmaf(vy, f.x, wB[0]); qB[0] = fmaf(vy, vy,  qB[0]);
        vx = vm.x; vy = vm.y;
        uA[1] = fmaf(vx, f.y, uA[1]); mA[1] = fmaf(vx, f.x, mA[1]);
        wA[1] = fmaf(vx, fl,  wA[1]); qA[1] = fmaf(vx, vx,  qA[1]);
        uB[1] = fmaf(vy, fr,  uB[1]); mB[1] = fmaf(vy, f.y, mB[1]);
        wB[1] = fmaf(vy, f.x, wB[1]); qB[1] = fmaf(vy, vy,  qB[1]);
        vx = vb.x; vy = vb.y;
        uA[2] = fmaf(vx, f.y, uA[2]); mA[2] = fmaf(vx, f.x, mA[2]);
        wA[2] = fmaf(vx, fl,  wA[2]); qA[2] = fmaf(vx, vx,  qA[2]);
        uB[2] = fmaf(vy, fr,  uB[2]); mB[2] = fmaf(vy, f.y, mB[2]);
        wB[2] = fmaf(vy, f.x, wB[2]); qB[2] = fmaf(vy, vy,  qB[2]);
    }

    // ---- redistribute + softmax, px A (col c0) ----
    float wgtA[KP], wgtB[KP];
    {
        float dot[KP], pn2[KP];
#pragma unroll
        for (int d = 0; d < 3; d++) {
            dot[d*3 + 0] = __shfl_up_sync(FULL, uB[d], 1);   // u(c0-1)
            dot[d*3 + 1] = mA[d];
            dot[d*3 + 2] = wB[d];                            // w(c0+1)
            pn2[d*3 + 0] = __shfl_up_sync(FULL, qB[d], 1);
            pn2[d*3 + 1] = qA[d];
            pn2[d*3 + 2] = qB[d];
        }
        weights9(dot, pn2, fnA, wgtA);
    }
    // ---- px B (col c1) ----
    {
        float dot[KP], pn2[KP];
#pragma unroll
        for (int d = 0; d < 3; d++) {
            dot[d*3 + 0] = uA[d];                            // u(c1-1)
            dot[d*3 + 1] = mB[d];
            dot[d*3 + 2] = __shfl_down_sync(FULL, wA[d], 1); // w(c1+1)
            pn2[d*3 + 0] = qA[d];
            pn2[d*3 + 1] = qB[d];
            pn2[d*3 + 2] = __shfl_down_sync(FULL, qA[d], 1);
        }
        weights9(dot, pn2, fnB, wgtB);
    }

    // pre-shuffled neighbor weights
    float wlB0 = __shfl_up_sync(FULL, wgtB[2], 1);
    float wlB1 = __shfl_up_sync(FULL, wgtB[5], 1);
    float wlB2 = __shfl_up_sync(FULL, wgtB[8], 1);
    float wrA0 = __shfl_down_sync(FULL, wgtA[0], 1);
    float wrA1 = __shfl_down_sync(FULL, wgtA[3], 1);
    float wrA2 = __shfl_down_sync(FULL, wgtA[6], 1);

    const bool st0 = (lane >= 1) && (c0 >= 0) && (c0 < WW);
    const bool st1 = (lane <= 30) && (c1 >= 0) && (c1 < WW);
    float* ob = out + rowoff + ca;

    // ---- pass 2 ----
#pragma unroll 4
    for (int c = 0; c < CC; c++) {
        const float* p = fup + c * HW;
        float2 vt = make_float2(0.0f, 0.0f);
        float2 vb = make_float2(0.0f, 0.0f);
        if (y0) vt = ld2(p - WW);
        float2 vm = ld2(p);
        if (y2) vb = ld2(p + WW);
        float2 f  = ld2(fep + c * HW);
        if (XE) {
            vt.x *= mx0; vt.y *= mx1;
            vm.x *= mx0; vm.y *= mx1;
            vb.x *= mx0; vb.y *= mx1;
        }

        float accA = vt.x * wgtA[1];
        accA = fmaf(vm.x, wgtA[4], accA);
        accA = fmaf(vb.x, wgtA[7], accA);
        accA = fmaf(vt.y, wgtA[2], accA);
        accA = fmaf(vm.y, wgtA[5], accA);
        accA = fmaf(vb.y, wgtA[8], accA);
        float accB = vt.y * wgtB[1];
        accB = fmaf(vm.y, wgtB[4], accB);
        accB = fmaf(vb.y, wgtB[7], accB);
        accB = fmaf(vt.x, wgtB[0], accB);
        accB = fmaf(vm.x, wgtB[3], accB);
        accB = fmaf(vb.x, wgtB[6], accB);
        float cl = vt.x * wlB0;
        cl = fmaf(vm.x, wlB1, cl);
        cl = fmaf(vb.x, wlB2, cl);
        float cr = vt.y * wrA0;
        cr = fmaf(vm.y, wrA1, cr);
        cr = fmaf(vb.y, wrA2, cr);

        float fromR = __shfl_down_sync(FULL, cl, 1);
        float fromL = __shfl_up_sync(FULL, cr, 1);

        float oA = accA + fromL + f.x;
        float oB = accB + fromR + f.y;

        float* q = ob + c * HW;
        if (st0 && st1) {
            *reinterpret_cast<float2*>(q) = make_float2(oA, oB);
        } else {
            if (st0) q[0] = oA;
            if (st1) q[1] = oB;
        }
    }
}

__global__ __launch_bounds__(NT, 8) void asfr_kernel(
    const float* __restrict__ fe,
    const float* __restrict__ fu,
    float* __restrict__ out)
{
    const int lane = threadIdx.x & 31;
    const int wid  = threadIdx.x >> 5;
    const int seg  = blockIdx.x;
    const int h    = blockIdx.y * WPB + wid;
    const int b    = blockIdx.z;

    if (seg == 0 || seg == NSEG - 1)
        body<true>(lane, seg, h, b, fe, fu, out);
    else
        body<false>(lane, seg, h, b, fe, fu, out);
}

extern "C" void kernel_launch(void* const* d_in, const int* in_sizes, int n_in,
                              void* d_out, int out_size)
{
    (void)in_sizes; (void)n_in; (void)out_size;
    const float* fe = (const float*)d_in[0];
    const float* fu = (const float*)d_in[1];
    float* out = (float*)d_out;

    dim3 grid(NSEG, HH / WPB, 4);
    asfr_kernel<<<grid, NT>>>(fe, fu, out);
}

// round 10
// speedup vs baseline: 1.1769x; 1.0962x over previous
#include <cuda_runtime.h>
#include <math.h>

#define CC 32
#define HH 256
#define WW 256
#define HWN (HH * WW)
#define KP 9
#define EPSF 1e-12f
#define SEGO 62                 // output pixels per warp
#define NWPB 1058               // warps per batch = ceil(HWN/SEGO)
#define NBATCH 4
#define NWTOT (NWPB * NBATCH)   // 4232
#define WPB 4                   // warps per block
#define NT (WPB * 32)
#define HW HWN

__device__ __forceinline__ float2 ld2(const float* p) {
    return *reinterpret_cast<const float2*>(p);
}

__device__ __forceinline__ void weights9(const float* __restrict__ dot,
                                         const float* __restrict__ pn2,
                                         float fn2,
                                         float* __restrict__ wgt)
{
    float fn = fmaxf(sqrtf(fn2), EPSF);
    float cs[KP], ed[KP];
    float cmax = -1e30f, emax = -1e30f;
#pragma unroll
    for (int k = 0; k < KP; k++) {
        float pn = fmaxf(sqrtf(pn2[k]), EPSF);
        float cv = dot[k] / (pn * fn);
        float d2 = pn2[k] + fn2 - 2.0f * dot[k];
        float ev = -sqrtf(fmaxf(d2, 0.0f));
        cs[k] = cv; ed[k] = ev;
        cmax = fmaxf(cmax, cv);
        emax = fmaxf(emax, ev);
    }
    float csum = 0.0f, esum = 0.0f;
#pragma unroll
    for (int k = 0; k < KP; k++) {
        cs[k] = __expf(cs[k] - cmax); csum += cs[k];
        ed[k] = __expf(ed[k] - emax); esum += ed[k];
    }
    float ci = 0.5f / csum, ei = 0.5f / esum;
#pragma unroll
    for (int k = 0; k < KP; k++) wgt[k] = cs[k] * ci + ed[k] * ei;
}

// MODE 0: clean interior (no masks). MODE 1: row-wrap inside window (link masks).
// MODE 2: y-edge / range edge (all masks).
template<int MODE>
__device__ __forceinline__ void body(
    int lane, int n0, int b,
    const float* __restrict__ fe,
    const float* __restrict__ fu,
    float* __restrict__ out)
{
    const unsigned FULL = 0xffffffffu;
    const int nA = n0 + 2 * lane;       // even flattened index
    const int nB = nA + 1;

    int ca = nA;
    if (MODE == 2) ca = min(max(nA, 0), HWN - 2);

    // link masks: left link (cA-1, cA) valid iff cA not at row start;
    // right link (cB, cB+1) valid iff cB+1 not at row start.
    float ml = 1.0f, mr = 1.0f;
    if (MODE >= 1) {
        ml = ((ca & 255) != 0) ? 1.0f : 0.0f;
        mr = (((ca + 2) & 255) != 0) ? 1.0f : 0.0f;
    }

    // value masks + safe vertical offsets (MODE 2 only)
    float mtA = 1.0f, mtB = 1.0f, mmA = 1.0f, mmB = 1.0f, mbA = 1.0f, mbB = 1.0f;
    int ot = -WW, obo = WW;
    if (MODE == 2) {
        mmA = (nA >= 0 && nA < HWN) ? 1.0f : 0.0f;
        mmB = (nB >= 0 && nB < HWN) ? 1.0f : 0.0f;
        mtA = (nA >= WW && nA < HWN) ? 1.0f : 0.0f;
        mtB = (nB >= WW && nB < HWN) ? 1.0f : 0.0f;
        mbA = (nA >= 0 && nA + WW < HWN) ? 1.0f : 0.0f;
        mbB = (nB >= 0 && nB + WW < HWN) ? 1.0f : 0.0f;
        ot  = (nA >= WW) ? -WW : 0;
        obo = (nA + 1 + WW < HWN) ? WW : 0;
    }

    const size_t base = ((size_t)b * CC) * HW + ca;
    const float* fup = fu + base;
    const float* fep = fe + base;

    // ---- pass 1: per-column scatter accumulators ----
    float uA[3] = {0,0,0}, mA[3] = {0,0,0}, wA[3] = {0,0,0}, qA[3] = {0,0,0};
    float uB[3] = {0,0,0}, mB[3] = {0,0,0}, wB[3] = {0,0,0}, qB[3] = {0,0,0};
    float fnA = 0.0f, fnB = 0.0f;

#pragma unroll 4
    for (int c = 0; c < CC; c++) {
        const float* p = fup + c * HW;
        float2 vt = ld2(p + ot);
        float2 vm = ld2(p);
        float2 vb = ld2(p + obo);
        float2 f  = ld2(fep + c * HW);
        if (MODE == 2) {
            vt.x *= mtA; vt.y *= mtB;
            vm.x *= mmA; vm.y *= mmB;
            vb.x *= mbA; vb.y *= mbB;
            f.x  *= mmA; f.y  *= mmB;
        }

        float fl = __shfl_up_sync(FULL, f.y, 1);    // f(cA-1)
        float fr = __shfl_down_sync(FULL, f.x, 1);  // f(cB+1)
        if (MODE >= 1) { fl *= ml; fr *= mr; }

        fnA = fmaf(f.x, f.x, fnA);
        fnB = fmaf(f.y, f.y, fnB);

        float vx, vy;
        vx = vt.x; vy = vt.y;
        uA[0] = fmaf(vx, f.y, uA[0]); mA[0] = fmaf(vx, f.x, mA[0]);
        wA[0] = fmaf(vx, fl,  wA[0]); qA[0] = fmaf(vx, vx,  qA[0]);
        uB[0] = fmaf(vy, fr,  uB[0]); mB[0] = fmaf(vy, f.y, mB[0]);
        wB[0] = fmaf(vy, f.x, wB[0]); qB[0] = fmaf(vy, vy,  qB[0]);
        vx = vm.x; vy = vm.y;
        uA[1] = fmaf(vx, f.y, uA[1]); mA[1] = fmaf(vx, f.x, mA[1]);
        wA[1] = fmaf(vx, fl,  wA[1]); qA[1] = fmaf(vx, vx,  qA[1]);
        uB[1] = fmaf(vy, fr,  uB[1]); mB[1] = fmaf(vy, f.y, mB[1]);
        wB[1] = fmaf(vy, f.x, wB[1]); qB[1] = fmaf(vy, vy,  qB[1]);
        vx = vb.x; vy = vb.y;
        uA[2] = fmaf(vx, f.y, uA[2]); mA[2] = fmaf(vx, f.x, mA[2]);
        wA[2] = fmaf(vx, fl,  wA[2]); qA[2] = fmaf(vx, vx,  qA[2]);
        uB[2] = fmaf(vy, fr,  uB[2]); mB[2] = fmaf(vy, f.y, mB[2]);
        wB[2] = fmaf(vy, f.x, wB[2]); qB[2] = fmaf(vy, vy,  qB[2]);
    }

    // ---- redistribute + softmax ----
    float wgtA[KP], wgtB[KP];
    {
        float dot[KP], pn2[KP];
#pragma unroll
        for (int d = 0; d < 3; d++) {
            float a0 = __shfl_up_sync(FULL, uB[d], 1);
            float q0 = __shfl_up_sync(FULL, qB[d], 1);
            if (MODE >= 1) { a0 *= ml; q0 *= ml; }
            dot[d*3 + 0] = a0;
            dot[d*3 + 1] = mA[d];
            dot[d*3 + 2] = wB[d];
            pn2[d*3 + 0] = q0;
            pn2[d*3 + 1] = qA[d];
            pn2[d*3 + 2] = qB[d];
        }
        weights9(dot, pn2, fnA, wgtA);
    }
    {
        float dot[KP], pn2[KP];
#pragma unroll
        for (int d = 0; d < 3; d++) {
            float a2 = __shfl_down_sync(FULL, wA[d], 1);
            float q2 = __shfl_down_sync(FULL, qA[d], 1);
            if (MODE >= 1) { a2 *= mr; q2 *= mr; }
            dot[d*3 + 0] = uA[d];
            dot[d*3 + 1] = mB[d];
            dot[d*3 + 2] = a2;
            pn2[d*3 + 0] = qA[d];
            pn2[d*3 + 1] = qB[d];
            pn2[d*3 + 2] = q2;
        }
        weights9(dot, pn2, fnB, wgtB);
    }

    // pre-shuffled neighbor weights (link-masked)
    float wlB0 = __shfl_up_sync(FULL, wgtB[2], 1);
    float wlB1 = __shfl_up_sync(FULL, wgtB[5], 1);
    float wlB2 = __shfl_up_sync(FULL, wgtB[8], 1);
    float wrA0 = __shfl_down_sync(FULL, wgtA[0], 1);
    float wrA1 = __shfl_down_sync(FULL, wgtA[3], 1);
    float wrA2 = __shfl_down_sync(FULL, wgtA[6], 1);
    if (MODE >= 1) {
        wlB0 *= ml; wlB1 *= ml; wlB2 *= ml;
        wrA0 *= mr; wrA1 *= mr; wrA2 *= mr;
    }

    bool st0 = (lane >= 1);
    bool st1 = (lane <= 30);
    if (MODE == 2) {
        st0 = st0 && (nA >= 0) && (nA < HWN);
        st1 = st1 && (nB >= 0) && (nB < HWN);
    }
    float* ob = out + base;

    // ---- pass 2 ----
#pragma unroll 4
    for (int c = 0; c < CC; c++) {
        const float* p = fup + c * HW;
        float2 vt = ld2(p + ot);
        float2 vm = ld2(p);
        float2 vb = ld2(p + obo);
        float2 f  = ld2(fep + c * HW);
        if (MODE == 2) {
            vt.x *= mtA; vt.y *= mtB;
            vm.x *= mmA; vm.y *= mmB;
            vb.x *= mbA; vb.y *= mbB;
        }

        float accA = vt.x * wgtA[1];
        accA = fmaf(vm.x, wgtA[4], accA);
        accA = fmaf(vb.x, wgtA[7], accA);
        accA = fmaf(vt.y, wgtA[2], accA);
        accA = fmaf(vm.y, wgtA[5], accA);
        accA = fmaf(vb.y, wgtA[8], accA);
        float accB = vt.y * wgtB[1];
        accB = fmaf(vm.y, wgtB[4], accB);
        accB = fmaf(vb.y, wgtB[7], accB);
        accB = fmaf(vt.x, wgtB[0], accB);
        accB = fmaf(vm.x, wgtB[3], accB);
        accB = fmaf(vb.x, wgtB[6], accB);
        float cl = vt.x * wlB0;
        cl = fmaf(vm.x, wlB1, cl);
        cl = fmaf(vb.x, wlB2, cl);
        float cr = vt.y * wrA0;
        cr = fmaf(vm.y, wrA1, cr);
        cr = fmaf(vb.y, wrA2, cr);

        float fromR = __shfl_down_sync(FULL, cl, 1);
        float fromL = __shfl_up_sync(FULL, cr, 1);

        float oA = accA + fromL + f.x;
        float oB = accB + fromR + f.y;

        float* q = ob + c * HW;
        if (st0 && st1) {
            *reinterpret_cast<float2*>(q) = make_float2(oA, oB);
        } else {
            if (st0) q[0] = oA;
            if (st1) q[1] = oB;
        }
    }
}

__global__ __launch_bounds__(NT, 8) void asfr_kernel(
    const float* __restrict__ fe,
    const float* __restrict__ fu,
    float* __restrict__ out)
{
    const int lane = threadIdx.x & 31;
    const int wid  = threadIdx.x >> 5;
    const int G    = blockIdx.x * WPB + wid;
    if (G >= NWTOT) return;
    const int b  = G / NWPB;
    const int W  = G - b * NWPB;
    const int n0 = W * SEGO - 2;

    if (W <= 4 || W >= 1052)
        body<2>(lane, n0, b, fe, fu, out);
    else if ((n0 & 255) >= 193)
        body<1>(lane, n0, b, fe, fu, out);
    else
        body<0>(lane, n0, b, fe, fu, out);
}

extern "C" void kernel_launch(void* const* d_in, const int* in_sizes, int n_in,
                              void* d_out, int out_size)
{
    (void)in_sizes; (void)n_in; (void)out_size;
    const float* fe = (const float*)d_in[0];
    const float* fu = (const float*)d_in[1];
    float* out = (float*)d_out;

    dim3 grid(NWTOT / WPB, 1, 1);   // 1058 blocks, zero idle warps
    asfr_kernel<<<grid, NT>>>(fe, fu, out);
}

// round 12
// speedup vs baseline: 1.3223x; 1.1236x over previous
#include <cuda_runtime.h>
#include <math.h>

#define CC 32
#define HH 256
#define WW 256
#define HWN (HH * WW)
#define KP 9
#define SEGO 62                 // output pixels per warp
#define NWPB 1058               // warps per batch = ceil(HWN/SEGO)
#define NBATCH 4
#define NWTOT (NWPB * NBATCH)   // 4232
#define WPB 4                   // warps per block
#define NT (WPB * 32)
#define HW HWN

__device__ __forceinline__ float2 ld2(const float* p) {
    return *reinterpret_cast<const float2*>(p);
}

__device__ __forceinline__ void weights9(const float* __restrict__ dot,
                                         const float* __restrict__ pn2,
                                         float fn2,
                                         float* __restrict__ wgt)
{
    // cos = dot * rsqrt(pn2) * rsqrt(fn2); dist = sqrt(pn2+fn2-2dot)
    // No max-subtraction: cos in [-1,1], -dist in [-inf,0] -> exp args bounded above by ~1.
    float rfn = rsqrtf(fmaxf(fn2, 1e-24f));
    float cs[KP], ed[KP];
    float csum = 0.0f, esum = 0.0f;
#pragma unroll
    for (int k = 0; k < KP; k++) {
        float rp = rsqrtf(fmaxf(pn2[k], 1e-24f));
        float cv = dot[k] * rp * rfn;
        float d2 = fmaxf(fmaf(-2.0f, dot[k], pn2[k] + fn2), 0.0f);
        float sd = d2 * rsqrtf(fmaxf(d2, 1e-30f));   // ~= sqrt(d2), 0-safe
        cs[k] = __expf(cv);
        csum += cs[k];
        ed[k] = __expf(-sd);
        esum += ed[k];
    }
    float ci = __fdividef(0.5f, csum);
    float ei = __fdividef(0.5f, esum);
#pragma unroll
    for (int k = 0; k < KP; k++) wgt[k] = cs[k] * ci + ed[k] * ei;
}

// MODE 0: clean interior (no masks). MODE 1: row-wrap inside window (link masks).
// MODE 2: y-edge / range edge (all masks).
template<int MODE>
__device__ __forceinline__ void body(
    int lane, int n0, int b,
    const float* __restrict__ fe,
    const float* __restrict__ fu,
    float* __restrict__ out)
{
    const unsigned FULL = 0xffffffffu;
    const int nA = n0 + 2 * lane;       // even flattened index
    const int nB = nA + 1;

    int ca = nA;
    if (MODE == 2) ca = min(max(nA, 0), HWN - 2);

    float ml = 1.0f, mr = 1.0f;
    if (MODE >= 1) {
        ml = ((ca & 255) != 0) ? 1.0f : 0.0f;
        mr = (((ca + 2) & 255) != 0) ? 1.0f : 0.0f;
    }

    float mtA = 1.0f, mtB = 1.0f, mmA = 1.0f, mmB = 1.0f, mbA = 1.0f, mbB = 1.0f;
    int ot = -WW, obo = WW;
    if (MODE == 2) {
        mmA = (nA >= 0 && nA < HWN) ? 1.0f : 0.0f;
        mmB = (nB >= 0 && nB < HWN) ? 1.0f : 0.0f;
        mtA = (nA >= WW && nA < HWN) ? 1.0f : 0.0f;
        mtB = (nB >= WW && nB < HWN) ? 1.0f : 0.0f;
        mbA = (nA >= 0 && nA + WW < HWN) ? 1.0f : 0.0f;
        mbB = (nB >= 0 && nB + WW < HWN) ? 1.0f : 0.0f;
        ot  = (nA >= WW) ? -WW : 0;
        obo = (nA + 1 + WW < HWN) ? WW : 0;
    }

    const size_t base = ((size_t)b * CC) * HW + ca;
    const float* fup = fu + base;
    const float* fep = fe + base;

    // ---- pass 1: per-column scatter accumulators ----
    float uA[3] = {0,0,0}, mA[3] = {0,0,0}, wA[3] = {0,0,0}, qA[3] = {0,0,0};
    float uB[3] = {0,0,0}, mB[3] = {0,0,0}, wB[3] = {0,0,0}, qB[3] = {0,0,0};
    float fnA = 0.0f, fnB = 0.0f;

#pragma unroll 4
    for (int c = 0; c < CC; c++) {
        const float* p = fup + c * HW;
        float2 vt = ld2(p + ot);
        float2 vm = ld2(p);
        float2 vb = ld2(p + obo);
        float2 f  = ld2(fep + c * HW);
        if (MODE == 2) {
            vt.x *= mtA; vt.y *= mtB;
            vm.x *= mmA; vm.y *= mmB;
            vb.x *= mbA; vb.y *= mbB;
            f.x  *= mmA; f.y  *= mmB;
        }

        float fl = __shfl_up_sync(FULL, f.y, 1);    // f(cA-1)
        float fr = __shfl_down_sync(FULL, f.x, 1);  // f(cB+1)
        if (MODE >= 1) { fl *= ml; fr *= mr; }

        fnA = fmaf(f.x, f.x, fnA);
        fnB = fmaf(f.y, f.y, fnB);

        float vx, vy;
        vx = vt.x; vy = vt.y;
        uA[0] = fmaf(vx, f.y, uA[0]); mA[0] = fmaf(vx, f.x, mA[0]);
        wA[0] = fmaf(vx, fl,  wA[0]); qA[0] = fmaf(vx, vx,  qA[0]);
        uB[0] = fmaf(vy, fr,  uB[0]); mB[0] = fmaf(vy, f.y, mB[0]);
        wB[0] = fmaf(vy, f.x, wB[0]); qB[0] = fmaf(vy, vy,  qB[0]);
        vx = vm.x; vy = vm.y;
        uA[1] = fmaf(vx, f.y, uA[1]); mA[1] = fmaf(vx, f.x, mA[1]);
        wA[1] = fmaf(vx, fl,  wA[1]); qA[1] = fmaf(vx, vx,  qA[1]);
        uB[1] = fmaf(vy, fr,  uB[1]); mB[1] = fmaf(vy, f.y, mB[1]);
        wB[1] = fmaf(vy, f.x, wB[1]); qB[1] = fmaf(vy, vy,  qB[1]);
        vx = vb.x; vy = vb.y;
        uA[2] = fmaf(vx, f.y, uA[2]); mA[2] = fmaf(vx, f.x, mA[2]);
        wA[2] = fmaf(vx, fl,  wA[2]); qA[2] = fmaf(vx, vx,  qA[2]);
        uB[2] = fmaf(vy, fr,  uB[2]); mB[2] = fmaf(vy, f.y, mB[2]);
        wB[2] = fmaf(vy, f.x, wB[2]); qB[2] = fmaf(vy, vy,  qB[2]);
    }

    // ---- redistribute + softmax ----
    float wgtA[KP], wgtB[KP];
    {
        float dot[KP], pn2[KP];
#pragma unroll
        for (int d = 0; d < 3; d++) {
            float a0 = __shfl_up_sync(FULL, uB[d], 1);
            float q0 = __shfl_up_sync(FULL, qB[d], 1);
            if (MODE >= 1) { a0 *= ml; q0 *= ml; }
            dot[d*3 + 0] = a0;
            dot[d*3 + 1] = mA[d];
            dot[d*3 + 2] = wB[d];
            pn2[d*3 + 0] = q0;
            pn2[d*3 + 1] = qA[d];
            pn2[d*3 + 2] = qB[d];
        }
        weights9(dot, pn2, fnA, wgtA);
    }
    {
        float dot[KP], pn2[KP];
#pragma unroll
        for (int d = 0; d < 3; d++) {
            float a2 = __shfl_down_sync(FULL, wA[d], 1);
            float q2 = __shfl_down_sync(FULL, qA[d], 1);
            if (MODE >= 1) { a2 *= mr; q2 *= mr; }
            dot[d*3 + 0] = uA[d];
            dot[d*3 + 1] = mB[d];
            dot[d*3 + 2] = a2;
            pn2[d*3 + 0] = qA[d];
            pn2[d*3 + 1] = qB[d];
            pn2[d*3 + 2] = q2;
        }
        weights9(dot, pn2, fnB, wgtB);
    }

    // pre-shuffled neighbor weights (link-masked)
    float wlB0 = __shfl_up_sync(FULL, wgtB[2], 1);
    float wlB1 = __shfl_up_sync(FULL, wgtB[5], 1);
    float wlB2 = __shfl_up_sync(FULL, wgtB[8], 1);
    float wrA0 = __shfl_down_sync(FULL, wgtA[0], 1);
    float wrA1 = __shfl_down_sync(FULL, wgtA[3], 1);
    float wrA2 = __shfl_down_sync(FULL, wgtA[6], 1);
    if (MODE >= 1) {
        wlB0 *= ml; wlB1 *= ml; wlB2 *= ml;
        wrA0 *= mr; wrA1 *= mr; wrA2 *= mr;
    }

    bool st0 = (lane >= 1);
    bool st1 = (lane <= 30);
    if (MODE == 2) {
        st0 = st0 && (nA >= 0) && (nA < HWN);
        st1 = st1 && (nB >= 0) && (nB < HWN);
    }
    float* ob = out + base;

    // ---- pass 2 ----
#pragma unroll 4
    for (int c = 0; c < CC; c++) {
        const float* p = fup + c * HW;
        float2 vt = ld2(p + ot);
        float2 vm = ld2(p);
        float2 vb = ld2(p + obo);
        float2 f  = ld2(fep + c * HW);
        if (MODE == 2) {
            vt.x *= mtA; vt.y *= mtB;
            vm.x *= mmA; vm.y *= mmB;
            vb.x *= mbA; vb.y *= mbB;
        }

        float accA = vt.x * wgtA[1];
        accA = fmaf(vm.x, wgtA[4], accA);
        accA = fmaf(vb.x, wgtA[7], accA);
        accA = fmaf(vt.y, wgtA[2], accA);
        accA = fmaf(vm.y, wgtA[5], accA);
        accA = fmaf(vb.y, wgtA[8], accA);
        float accB = vt.y * wgtB[1];
        accB = fmaf(vm.y, wgtB[4], accB);
        accB = fmaf(vb.y, wgtB[7], accB);
        accB = fmaf(vt.x, wgtB[0], accB);
        accB = fmaf(vm.x, wgtB[3], accB);
        accB = fmaf(vb.x, wgtB[6], accB);
        float cl = vt.x * wlB0;
        cl = fmaf(vm.x, wlB1, cl);
        cl = fmaf(vb.x, wlB2, cl);
        float cr = vt.y * wrA0;
        cr = fmaf(vm.y, wrA1, cr);
        cr = fmaf(vb.y, wrA2, cr);

        float fromR = __shfl_down_sync(FULL, cl, 1);
        float fromL = __shfl_up_sync(FULL, cr, 1);

        float oA = accA + fromL + f.x;
        float oB = accB + fromR + f.y;

        float* q = ob + c * HW;
        if (st0 && st1) {
            *reinterpret_cast<float2*>(q) = make_float2(oA, oB);
        } else {
            if (st0) q[0] = oA;
            if (st1) q[1] = oB;
        }
    }
}

__global__ __launch_bounds__(NT, 8) void asfr_kernel(
    const float* __restrict__ fe,
    const float* __restrict__ fu,
    float* __restrict__ out)
{
    const int lane = threadIdx.x & 31;
    const int wid  = threadIdx.x >> 5;
    const int G    = blockIdx.x * WPB + wid;
    if (G >= NWTOT) return;
    const int b  = G / NWPB;
    const int W  = G - b * NWPB;
    const int n0 = W * SEGO - 2;

    if (W <= 4 || W >= 1052)
        body<2>(lane, n0, b, fe, fu, out);
    else if ((n0 & 255) >= 193)
        body<1>(lane, n0, b, fe, fu, out);
    else
        body<0>(lane, n0, b, fe, fu, out);
}

extern "C" void kernel_launch(void* const* d_in, const int* in_sizes, int n_in,
                              void* d_out, int out_size)
{
    (void)in_sizes; (void)n_in; (void)out_size;
    const float* fe = (const float*)d_in[0];
    const float* fu = (const float*)d_in[1];
    float* out = (float*)d_out;

    dim3 grid(NWTOT / WPB, 1, 1);   // 1058 blocks, zero idle warps
    asfr_kernel<<<grid, NT>>>(fe, fu, out);
}

// round 13
// speedup vs baseline: 1.4964x; 1.1316x over previous
#include <cuda_runtime.h>
#include <math.h>

#define CC 32
#define HH 256
#define WW 256
#define HWN (HH * WW)
#define KP 9
#define SEGO 62                 // output pixels per warp
#define NWPB 1058               // warps per batch = ceil(HWN/SEGO)
#define NBATCH 4
#define NWTOT (NWPB * NBATCH)   // 4232
#define NT 32                   // ONE warp per block (pure scheduling container)
#define HW HWN

__device__ __forceinline__ float2 ld2(const float* p) {
    return *reinterpret_cast<const float2*>(p);
}

__device__ __forceinline__ void weights9(const float* __restrict__ dot,
                                         const float* __restrict__ pn2,
                                         float fn2,
                                         float* __restrict__ wgt)
{
    float rfn = rsqrtf(fmaxf(fn2, 1e-24f));
    float cs[KP], ed[KP];
    float csum = 0.0f, esum = 0.0f;
#pragma unroll
    for (int k = 0; k < KP; k++) {
        float rp = rsqrtf(fmaxf(pn2[k], 1e-24f));
        float cv = dot[k] * rp * rfn;
        float d2 = fmaxf(fmaf(-2.0f, dot[k], pn2[k] + fn2), 0.0f);
        float sd = d2 * rsqrtf(fmaxf(d2, 1e-30f));   // ~= sqrt(d2), 0-safe
        cs[k] = __expf(cv);
        csum += cs[k];
        ed[k] = __expf(-sd);
        esum += ed[k];
    }
    float ci = __fdividef(0.5f, csum);
    float ei = __fdividef(0.5f, esum);
#pragma unroll
    for (int k = 0; k < KP; k++) wgt[k] = cs[k] * ci + ed[k] * ei;
}

// MODE 0: clean interior. MODE 1: row-wrap inside window. MODE 2: y/range edge.
template<int MODE>
__device__ __forceinline__ void body(
    int lane, int n0, int b,
    const float* __restrict__ fe,
    const float* __restrict__ fu,
    float* __restrict__ out)
{
    const unsigned FULL = 0xffffffffu;
    const int nA = n0 + 2 * lane;
    const int nB = nA + 1;

    int ca = nA;
    if (MODE == 2) ca = min(max(nA, 0), HWN - 2);

    float ml = 1.0f, mr = 1.0f;
    if (MODE >= 1) {
        ml = ((ca & 255) != 0) ? 1.0f : 0.0f;
        mr = (((ca + 2) & 255) != 0) ? 1.0f : 0.0f;
    }

    float mtA = 1.0f, mtB = 1.0f, mmA = 1.0f, mmB = 1.0f, mbA = 1.0f, mbB = 1.0f;
    int ot = -WW, obo = WW;
    if (MODE == 2) {
        mmA = (nA >= 0 && nA < HWN) ? 1.0f : 0.0f;
        mmB = (nB >= 0 && nB < HWN) ? 1.0f : 0.0f;
        mtA = (nA >= WW && nA < HWN) ? 1.0f : 0.0f;
        mtB = (nB >= WW && nB < HWN) ? 1.0f : 0.0f;
        mbA = (nA >= 0 && nA + WW < HWN) ? 1.0f : 0.0f;
        mbB = (nB >= 0 && nB + WW < HWN) ? 1.0f : 0.0f;
        ot  = (nA >= WW) ? -WW : 0;
        obo = (nA + 1 + WW < HWN) ? WW : 0;
    }

    const size_t base = ((size_t)b * CC) * HW + ca;
    const float* fup = fu + base;
    const float* fep = fe + base;

    // ---- pass 1: per-column scatter accumulators ----
    float uA[3] = {0,0,0}, mA[3] = {0,0,0}, wA[3] = {0,0,0}, qA[3] = {0,0,0};
    float uB[3] = {0,0,0}, mB[3] = {0,0,0}, wB[3] = {0,0,0}, qB[3] = {0,0,0};
    float fnA = 0.0f, fnB = 0.0f;

#pragma unroll 4
    for (int c = 0; c < CC; c++) {
        const float* p = fup + c * HW;
        float2 vt = ld2(p + ot);
        float2 vm = ld2(p);
        float2 vb = ld2(p + obo);
        float2 f  = ld2(fep + c * HW);
        if (MODE == 2) {
            vt.x *= mtA; vt.y *= mtB;
            vm.x *= mmA; vm.y *= mmB;
            vb.x *= mbA; vb.y *= mbB;
            f.x  *= mmA; f.y  *= mmB;
        }

        float fl = __shfl_up_sync(FULL, f.y, 1);    // f(cA-1)
        float fr = __shfl_down_sync(FULL, f.x, 1);  // f(cB+1)
        if (MODE >= 1) { fl *= ml; fr *= mr; }

        fnA = fmaf(f.x, f.x, fnA);
        fnB = fmaf(f.y, f.y, fnB);

        float vx, vy;
        vx = vt.x; vy = vt.y;
        uA[0] = fmaf(vx, f.y, uA[0]); mA[0] = fmaf(vx, f.x, mA[0]);
        wA[0] = fmaf(vx, fl,  wA[0]); qA[0] = fmaf(vx, vx,  qA[0]);
        uB[0] = fmaf(vy, fr,  uB[0]); mB[0] = fmaf(vy, f.y, mB[0]);
        wB[0] = fmaf(vy, f.x, wB[0]); qB[0] = fmaf(vy, vy,  qB[0]);
        vx = vm.x; vy = vm.y;
        uA[1] = fmaf(vx, f.y, uA[1]); mA[1] = fmaf(vx, f.x, mA[1]);
        wA[1] = fmaf(vx, fl,  wA[1]); qA[1] = fmaf(vx, vx,  qA[1]);
        uB[1] = fmaf(vy, fr,  uB[1]); mB[1] = fmaf(vy, f.y, mB[1]);
        wB[1] = fmaf(vy, f.x, wB[1]); qB[1] = fmaf(vy, vy,  qB[1]);
        vx = vb.x; vy = vb.y;
        uA[2] = fmaf(vx, f.y, uA[2]); mA[2] = fmaf(vx, f.x, mA[2]);
        wA[2] = fmaf(vx, fl,  wA[2]); qA[2] = fmaf(vx, vx,  qA[2]);
        uB[2] = fmaf(vy, fr,  uB[2]); mB[2] = fmaf(vy, f.y, mB[2]);
        wB[2] = fmaf(vy, f.x, wB[2]); qB[2] = fmaf(vy, vy,  qB[2]);
    }

    // ---- redistribute + softmax ----
    float wgtA[KP], wgtB[KP];
    {
        float dot[KP], pn2[KP];
#pragma unroll
        for (int d = 0; d < 3; d++) {
            float a0 = __shfl_up_sync(FULL, uB[d], 1);
            float q0 = __shfl_up_sync(FULL, qB[d], 1);
            if (MODE >= 1) { a0 *= ml; q0 *= ml; }
            dot[d*3 + 0] = a0;
            dot[d*3 + 1] = mA[d];
            dot[d*3 + 2] = wB[d];
            pn2[d*3 + 0] = q0;
            pn2[d*3 + 1] = qA[d];
            pn2[d*3 + 2] = qB[d];
        }
        weights9(dot, pn2, fnA, wgtA);
    }
    {
        float dot[KP], pn2[KP];
#pragma unroll
        for (int d = 0; d < 3; d++) {
            float a2 = __shfl_down_sync(FULL, wA[d], 1);
            float q2 = __shfl_down_sync(FULL, qA[d], 1);
            if (MODE >= 1) { a2 *= mr; q2 *= mr; }
            dot[d*3 + 0] = uA[d];
            dot[d*3 + 1] = mB[d];
            dot[d*3 + 2] = a2;
            pn2[d*3 + 0] = qA[d];
            pn2[d*3 + 1] = qB[d];
            pn2[d*3 + 2] = q2;
        }
        weights9(dot, pn2, fnB, wgtB);
    }

    // pre-shuffled neighbor weights (link-masked)
    float wlB0 = __shfl_up_sync(FULL, wgtB[2], 1);
    float wlB1 = __shfl_up_sync(FULL, wgtB[5], 1);
    float wlB2 = __shfl_up_sync(FULL, wgtB[8], 1);
    float wrA0 = __shfl_down_sync(FULL, wgtA[0], 1);
    float wrA1 = __shfl_down_sync(FULL, wgtA[3], 1);
    float wrA2 = __shfl_down_sync(FULL, wgtA[6], 1);
    if (MODE >= 1) {
        wlB0 *= ml; wlB1 *= ml; wlB2 *= ml;
        wrA0 *= mr; wrA1 *= mr; wrA2 *= mr;
    }

    bool st0 = (lane >= 1);
    bool st1 = (lane <= 30);
    if (MODE == 2) {
        st0 = st0 && (nA >= 0) && (nA < HWN);
        st1 = st1 && (nB >= 0) && (nB < HWN);
    }
    float* ob = out + base;

    // ---- pass 2 (reverse channel order: last pass-1 channels are L1-hot) ----
#pragma unroll 4
    for (int ci = 0; ci < CC; ci++) {
        const int c = CC - 1 - ci;
        const float* p = fup + c * HW;
        float2 vt = ld2(p + ot);
        float2 vm = ld2(p);
        float2 vb = ld2(p + obo);
        float2 f  = ld2(fep + c * HW);
        if (MODE == 2) {
            vt.x *= mtA; vt.y *= mtB;
            vm.x *= mmA; vm.y *= mmB;
            vb.x *= mbA; vb.y *= mbB;
        }

        float accA = vt.x * wgtA[1];
        accA = fmaf(vm.x, wgtA[4], accA);
        accA = fmaf(vb.x, wgtA[7], accA);
        accA = fmaf(vt.y, wgtA[2], accA);
        accA = fmaf(vm.y, wgtA[5], accA);
        accA = fmaf(vb.y, wgtA[8], accA);
        float accB = vt.y * wgtB[1];
        accB = fmaf(vm.y, wgtB[4], accB);
        accB = fmaf(vb.y, wgtB[7], accB);
        accB = fmaf(vt.x, wgtB[0], accB);
        accB = fmaf(vm.x, wgtB[3], accB);
        accB = fmaf(vb.x, wgtB[6], accB);
        float cl = vt.x * wlB0;
        cl = fmaf(vm.x, wlB1, cl);
        cl = fmaf(vb.x, wlB2, cl);
        float cr = vt.y * wrA0;
        cr = fmaf(vm.y, wrA1, cr);
        cr = fmaf(vb.y, wrA2, cr);

        float fromR = __shfl_down_sync(FULL, cl, 1);
        float fromL = __shfl_up_sync(FULL, cr, 1);

        float oA = accA + fromL + f.x;
        float oB = accB + fromR + f.y;

        float* q = ob + c * HW;
        if (st0 && st1) {
            *reinterpret_cast<float2*>(q) = make_float2(oA, oB);
        } else {
            if (st0) q[0] = oA;
            if (st1) q[1] = oB;
        }
    }
}

__global__ __launch_bounds__(NT, 32) void asfr_kernel(
    const float* __restrict__ fe,
    const float* __restrict__ fu,
    float* __restrict__ out)
{
    const int lane = threadIdx.x & 31;
    const int G    = blockIdx.x;         // one warp per block
    const int b    = G / NWPB;
    const int W    = G - b * NWPB;
    const int n0   = W * SEGO - 2;

    if (W <= 4 || W >= 1052)
        body<2>(lane, n0, b, fe, fu, out);
    else if ((n0 & 255) >= 193)
        body<1>(lane, n0, b, fe, fu, out);
    else
        body<0>(lane, n0, b, fe, fu, out);
}

extern "C" void kernel_launch(void* const* d_in, const int* in_sizes, int n_in,
                              void* d_out, int out_size)
{
    (void)in_sizes; (void)n_in; (void)out_size;
    const float* fe = (const float*)d_in[0];
    const float* fu = (const float*)d_in[1];
    float* out = (float*)d_out;

    asfr_kernel<<<NWTOT, NT>>>(fe, fu, out);   // 4232 one-warp blocks
}